// round 7
// baseline (speedup 1.0000x reference)
#include <cuda_runtime.h>
#include <cstdint>
#include <math.h>

#define FULL 0xffffffffu
#define LOG2E 1.4426950408889634f
#define LN2   0.6931471805599453f
#define NWARPS_TOTAL 1776           // 444 CTAs * 4 warps
#define NPAIRS 4096                 // 8192 samples / 2

// Precomputed log_softmax(W_m, axis=0) * LOG2E  [32,32,32] (16B aligned)
// g_a0b: a0 in log2 units, blocked lane layout: lane i holds k' = 4(i%8)+(i>>3)
__device__ __align__(16) float g_wl2[32 * 32 * 32];
__device__ float g_a0b[32];

__device__ __forceinline__ float ex2f(float x) {
    float y; asm("ex2.approx.f32 %0, %1;" : "=f"(y) : "f"(x)); return y;
}
__device__ __forceinline__ float lg2f(float x) {
    float y; asm("lg2.approx.f32 %0, %1;" : "=f"(y) : "f"(x)); return y;
}
__device__ __forceinline__ void cpa16(unsigned int dst, const float4* src) {
    asm volatile("cp.async.cg.shared.global [%0], [%1], 16;" :: "r"(dst), "l"(src));
}
#define CP_COMMIT() asm volatile("cp.async.commit_group;" ::: "memory")
#define CP_WAIT1()  asm volatile("cp.async.wait_group 1;" ::: "memory")

// ---------------------------------------------------------------------------
// Prep: block m (32 blocks), thread kp: log_softmax over k of W[m,k,kp] * LOG2E.
// Block 0 also computes a0 (log2 units, blocked lane layout).
// ---------------------------------------------------------------------------
__global__ void tt_prep_kernel(const float* __restrict__ W,
                               const float* __restrict__ wk0) {
    int m = blockIdx.x, kp = threadIdx.x;

    float v[32];
    float mx = -INFINITY;
#pragma unroll
    for (int k = 0; k < 32; k++) {
        v[k] = W[m * 1024 + k * 32 + kp];
        mx = fmaxf(mx, v[k]);
    }
    float s = 0.f;
#pragma unroll
    for (int k = 0; k < 32; k++) s += expf(v[k] - mx);
    float lse = mx + logf(s);
#pragma unroll
    for (int k = 0; k < 32; k++)
        g_wl2[m * 1024 + k * 32 + kp] = (v[k] - lse) * LOG2E;

    if (m == 0) {
        float m2 = -INFINITY;
#pragma unroll
        for (int k = 0; k < 32; k++) m2 = fmaxf(m2, wk0[k]);
        float s2 = 0.f;
#pragma unroll
        for (int k = 0; k < 32; k++) s2 += expf(wk0[k] - m2);
        float lse0 = m2 + logf(s2);
        int kp0 = 4 * (kp & 7) + (kp >> 3);   // blocked layout
        g_a0b[kp] = (wk0[kp0] - lse0) * LOG2E;
    }
}

// ---------------------------------------------------------------------------
// Main: persistent, 444 CTAs x 128 threads (3 CTAs/SM, single wave).
// Each WARP is an independent work unit: it owns an 8 KB x2 double buffer in
// smem and a private cp.async stream (wait_group + __syncwarp only — no
// __syncthreads in the main loop). A warp processes sample-pairs
// p = gwid, gwid+1776, ... ; the prefetch is flattened across pair boundaries
// so the pipeline never drains. W slices are read via __ldg (L2/L1 resident).
// Compute core: blocked lane layout (lane i holds k' = 4(i%8)+(i>>3)),
// one-pass stable logsumexp in the log2 domain (ref = lane 0's b).
// ---------------------------------------------------------------------------
__global__ void __launch_bounds__(128)
tt_main_kernel(const float* __restrict__ L, float* __restrict__ out) {
    extern __shared__ float4 sbuf[];   // 4 warps * 2 buffers * 512 f4 = 64 KB
    const int wid  = threadIdx.x >> 5;
    const int lane = threadIdx.x & 31;
    const int rsub = lane >> 3;
    const int srcb = lane & 24;
    const int gwid = blockIdx.x * 4 + wid;

    const float4* W4  = (const float4*)g_wl2;
    const float4* Lg  = (const float4*)L;
    float4*       wbuf = sbuf + wid * 1024;          // this warp's region
    unsigned int  sbw  = (unsigned int)__cvta_generic_to_shared(wbuf);

    const float a0 = g_a0b[lane];

    int p = gwid;                                    // always < NPAIRS here
    const float4* Lp = Lg + (size_t)(2 * p) * 8192;

    // Prologue: prefetch (p, m=0) into buffer 0.
#pragma unroll
    for (int j = 0; j < 16; j++) {
        int i = j * 32 + lane;                       // 0..511
        cpa16(sbw + (unsigned int)i * 16u, Lp + ((i >> 8) * 8192 + (i & 255)));
    }
    CP_COMMIT();

    int buf = 0;

#pragma unroll 1
    while (true) {
        float bA = a0, bB = a0;

#pragma unroll 1
        for (int m = 0; m < 32; m++) {
            // Prefetch the next flattened step into the other buffer.
            {
                int pn = (m == 31) ? p + NWARPS_TOTAL : p;
                int mn = (m == 31) ? 0 : m + 1;
                if (pn < NPAIRS) {
                    const float4* Ln = Lg + (size_t)(2 * pn) * 8192 + mn * 256;
                    unsigned int db = sbw + (unsigned int)(buf ^ 1) * 8192u;
#pragma unroll
                    for (int j = 0; j < 16; j++) {
                        int i = j * 32 + lane;
                        cpa16(db + (unsigned int)i * 16u,
                              Ln + ((i >> 8) * 8192 + (i & 255)));
                    }
                }
                CP_COMMIT();
            }
            CP_WAIT1();          // this warp's current buffer is complete
            __syncwarp();

            const float4* bufL = wbuf + buf * 512;
            const float4* wm   = W4 + m * 256;

            const float refA = __shfl_sync(FULL, bA, 0);
            const float refB = __shfl_sync(FULL, bB, 0);

            float4 accA = make_float4(0.f, 0.f, 0.f, 0.f);
            float4 accB = make_float4(0.f, 0.f, 0.f, 0.f);

#pragma unroll
            for (int blk = 0; blk < 8; blk++) {
                float4 w4  = __ldg(wm + blk * 32 + lane);
                float4 l4A = bufL[blk * 32 + lane];
                float4 l4B = bufL[256 + blk * 32 + lane];
                float pA = ex2f(__shfl_sync(FULL, bA, srcb | blk) - refA);
                float pB = ex2f(__shfl_sync(FULL, bB, srcb | blk) - refB);

                accA.x = fmaf(pA, ex2f(fmaf(l4A.x, LOG2E, w4.x)), accA.x);
                accA.y = fmaf(pA, ex2f(fmaf(l4A.y, LOG2E, w4.y)), accA.y);
                accA.z = fmaf(pA, ex2f(fmaf(l4A.z, LOG2E, w4.z)), accA.z);
                accA.w = fmaf(pA, ex2f(fmaf(l4A.w, LOG2E, w4.w)), accA.w);
                accB.x = fmaf(pB, ex2f(fmaf(l4B.x, LOG2E, w4.x)), accB.x);
                accB.y = fmaf(pB, ex2f(fmaf(l4B.y, LOG2E, w4.y)), accB.y);
                accB.z = fmaf(pB, ex2f(fmaf(l4B.z, LOG2E, w4.z)), accB.z);
                accB.w = fmaf(pB, ex2f(fmaf(l4B.w, LOG2E, w4.w)), accB.w);
            }
            __syncwarp();   // all reads of this buffer done before it refills

            // Sum over the 4 row-residue lanes sharing each k' group.
#pragma unroll
            for (int off = 8; off <= 16; off <<= 1) {
                accA.x += __shfl_xor_sync(FULL, accA.x, off);
                accA.y += __shfl_xor_sync(FULL, accA.y, off);
                accA.z += __shfl_xor_sync(FULL, accA.z, off);
                accA.w += __shfl_xor_sync(FULL, accA.w, off);
                accB.x += __shfl_xor_sync(FULL, accB.x, off);
                accB.y += __shfl_xor_sync(FULL, accB.y, off);
                accB.z += __shfl_xor_sync(FULL, accB.z, off);
                accB.w += __shfl_xor_sync(FULL, accB.w, off);
            }

            // Stay in blocked layout: this lane keeps component rsub.
            float vA = (rsub & 2) ? ((rsub & 1) ? accA.w : accA.z)
                                  : ((rsub & 1) ? accA.y : accA.x);
            float vB = (rsub & 2) ? ((rsub & 1) ? accB.w : accB.z)
                                  : ((rsub & 1) ? accB.y : accB.x);

            bA = lg2f(vA) + refA;
            bB = lg2f(vB) + refB;

            buf ^= 1;
        }

        // Final logsumexp across lanes (layout is a permutation — invariant).
        float mA = bA, mB = bB;
#pragma unroll
        for (int off = 16; off; off >>= 1) {
            mA = fmaxf(mA, __shfl_xor_sync(FULL, mA, off));
            mB = fmaxf(mB, __shfl_xor_sync(FULL, mB, off));
        }
        float eA = ex2f(bA - mA);
        float eB = ex2f(bB - mB);
#pragma unroll
        for (int off = 16; off; off >>= 1) {
            eA += __shfl_xor_sync(FULL, eA, off);
            eB += __shfl_xor_sync(FULL, eB, off);
        }
        if (lane == 0) {
            out[2 * p]     = (mA + lg2f(eA)) * LN2;
            out[2 * p + 1] = (mB + lg2f(eB)) * LN2;
        }

        p += NWARPS_TOTAL;
        if (p >= NPAIRS) break;
        Lp = Lg + (size_t)(2 * p) * 8192;
    }
}

// ---------------------------------------------------------------------------
// Launch contract
// ---------------------------------------------------------------------------
extern "C" void kernel_launch(void* const* d_in, const int* in_sizes, int n_in,
                              void* d_out, int out_size) {
    const float* L   = (const float*)d_in[0];   // [8192, 32, 32, 32]
    const float* wk0 = (const float*)d_in[1];   // [1, 32]
    const float* W   = (const float*)d_in[2];   // [32, 32, 32]
    float* out = (float*)d_out;                 // [8192]

    (void)in_sizes; (void)n_in; (void)out_size;

    cudaFuncSetAttribute(tt_main_kernel,
                         cudaFuncAttributeMaxDynamicSharedMemorySize, 65536);

    tt_prep_kernel<<<32, 32>>>(W, wk0);
    // Persistent: 444 CTAs = 3 per SM, single wave; warps stride over pairs.
    tt_main_kernel<<<444, 128, 65536>>>(L, out);
}